// round 7
// baseline (speedup 1.0000x reference)
#include <cuda_runtime.h>

// VectorQuantizer: inputs [32, 64, 64, 64] fp32 NCHW (C = D = 64), embedding [512, 64] fp32.
// Bit-exact replication of the reference fp32 arithmetic:
//   A   = sum_d fl(x_d * x_d)            (sequential mul-then-add chain, ascending d)
//   e2k = sum_d fl(e_d * e_d)            (sequential mul-then-add chain, ascending d)
//   s_k = FMA-chain_d (x_d * e_dk)       (ascending d, single accumulator)
//   dist_k = fl( fl(A + e2k) + fl(-2*s_k) )
//   argmin: first-occurrence. Implemented as: per-16-code-chunk FMNMX min -> smem;
//           ascending strict-< scan over chunk minima (first chunk wins), then bit-exact
//           recompute of the winning chunk and first-j equality match.
//   out = fl(x + fl(q - x))              (exact straight-through-estimator rounding)
//
// Perf: 2 pixels/thread share every codebook LDS.128. Argmin bookkeeping moved off the
// critical loop (regs freed -> deeper LDS software pipelining).

#define NUM_CODES 512
#define DIMS      64
#define TPB       256
#define NPIX      (32 * 64 * 64)          // 131072 pixels
#define NPAIRS    (NPIX / 2)              // 65536: pair (n, n+NPAIRS)
#define IMG_STRIDE (64 * 4096)            // floats per image (C*H*W)
#define PAIR_OFF  (16 * IMG_STRIDE)       // pixel n+65536 is image b+16, same (h,w)
#define NCHUNK    (NUM_CODES / 16)        // 32 chunks of 16 codes
#define CB_FLOATS (DIMS * NUM_CODES + NUM_CODES)
#define CM_FLOATS (NCHUNK * 2 * TPB)      // per-thread chunk minima [chunk][px][tid]
#define SMEM_BYTES ((CB_FLOATS + CM_FLOATS) * 4)   // 133120 + 65536 = 198656 B
#define GRID 152

typedef unsigned long long ull;

__device__ __forceinline__ ull ffma2(ull a, ull b, ull c) {
    ull d;
    asm("fma.rn.f32x2 %0, %1, %2, %3;" : "=l"(d) : "l"(a), "l"(b), "l"(c));
    return d;
}
__device__ __forceinline__ ull fadd2(ull a, ull b) {
    ull d;
    asm("add.rn.f32x2 %0, %1, %2;" : "=l"(d) : "l"(a), "l"(b));
    return d;
}
__device__ __forceinline__ ull fmul2(ull a, ull b) {
    ull d;
    asm("mul.rn.f32x2 %0, %1, %2;" : "=l"(d) : "l"(a), "l"(b));
    return d;
}
__device__ __forceinline__ ull pack2(float x) {
    ull r;
    asm("mov.b64 %0, {%1, %1};" : "=l"(r) : "f"(x));
    return r;
}
__device__ __forceinline__ void unpack2(ull v, float& lo, float& hi) {
    asm("mov.b64 {%0, %1}, %2;" : "=f"(lo), "=f"(hi) : "l"(v));
}

// Bit-exact distances for one 16-code chunk (same op order as the main sweep).
__device__ __forceinline__ void chunk_dists(const float* __restrict__ x, ull Ap, ull neg2,
                                            const float* __restrict__ Es,
                                            const float* __restrict__ e2s,
                                            int k0, float* __restrict__ dist) {
    ull acc[8];
    #pragma unroll
    for (int j = 0; j < 8; ++j) acc[j] = 0ull;
    #pragma unroll
    for (int d = 0; d < DIMS; ++d) {
        const ull xp = pack2(x[d]);
        const ulonglong2* p = reinterpret_cast<const ulonglong2*>(Es + d * NUM_CODES + k0);
        ulonglong2 q0 = p[0], q1 = p[1], q2 = p[2], q3 = p[3];
        acc[0] = ffma2(xp, q0.x, acc[0]);
        acc[1] = ffma2(xp, q0.y, acc[1]);
        acc[2] = ffma2(xp, q1.x, acc[2]);
        acc[3] = ffma2(xp, q1.y, acc[3]);
        acc[4] = ffma2(xp, q2.x, acc[4]);
        acc[5] = ffma2(xp, q2.y, acc[5]);
        acc[6] = ffma2(xp, q3.x, acc[6]);
        acc[7] = ffma2(xp, q3.y, acc[7]);
    }
    const ull* e2q = reinterpret_cast<const ull*>(e2s + k0);
    #pragma unroll
    for (int j = 0; j < 8; ++j) {
        const ull dd = fadd2(fadd2(Ap, e2q[j]), fmul2(neg2, acc[j]));
        unpack2(dd, dist[2 * j], dist[2 * j + 1]);
    }
}

__global__ __launch_bounds__(TPB, 1)
void vq_kernel(const float* __restrict__ in,
               const float* __restrict__ emb,
               float* __restrict__ out) {
    extern __shared__ float smem[];
    float* Es   = smem;                       // transposed codebook [DIMS][NUM_CODES]
    float* e2s  = smem + DIMS * NUM_CODES;    // ||e_k||^2, [NUM_CODES]
    float* cmin = smem + CB_FLOATS;           // [NCHUNK][2][TPB] per-thread chunk minima

    const int tid = threadIdx.x;

    // ---- Stage codebook into smem, transposed, + sequential-chain squared norms ----
    #pragma unroll
    for (int kk = 0; kk < 2; ++kk) {
        const int k = tid + kk * TPB;
        const float4* row = reinterpret_cast<const float4*>(emb + k * DIMS);
        float s = 0.0f;
        #pragma unroll
        for (int j = 0; j < DIMS / 4; ++j) {
            float4 v = row[j];
            Es[(4 * j + 0) * NUM_CODES + k] = v.x;
            Es[(4 * j + 1) * NUM_CODES + k] = v.y;
            Es[(4 * j + 2) * NUM_CODES + k] = v.z;
            Es[(4 * j + 3) * NUM_CODES + k] = v.w;
            s = __fadd_rn(s, __fmul_rn(v.x, v.x));
            s = __fadd_rn(s, __fmul_rn(v.y, v.y));
            s = __fadd_rn(s, __fmul_rn(v.z, v.z));
            s = __fadd_rn(s, __fmul_rn(v.w, v.w));
        }
        e2s[k] = s;
    }
    __syncthreads();

    const ull neg2 = pack2(-2.0f);
    const int totalThreads = GRID * TPB;

    for (int p = blockIdx.x * TPB + tid; p < NPAIRS; p += totalThreads) {
        const int base0 = ((p >> 12) * IMG_STRIDE) + (p & 4095);
        const float* px0 = in + base0;
        const float* px1 = in + base0 + PAIR_OFF;

        float x0[DIMS], x1[DIMS];
        #pragma unroll
        for (int d = 0; d < DIMS; ++d) x0[d] = px0[d << 12];
        #pragma unroll
        for (int d = 0; d < DIMS; ++d) x1[d] = px1[d << 12];

        // A = ||x||^2 : strict sequential mul-then-add chain, ascending d.
        float A0 = 0.0f, A1 = 0.0f;
        #pragma unroll
        for (int d = 0; d < DIMS; ++d) A0 = __fadd_rn(A0, __fmul_rn(x0[d], x0[d]));
        #pragma unroll
        for (int d = 0; d < DIMS; ++d) A1 = __fadd_rn(A1, __fmul_rn(x1[d], x1[d]));
        const ull A0p = pack2(A0);
        const ull A1p = pack2(A1);

        // ---- Main sweep: per-chunk distances -> FMNMX min -> smem ----
        #pragma unroll 1
        for (int k0 = 0; k0 < NUM_CODES; k0 += 16) {
            ull acc0[8], acc1[8];
            #pragma unroll
            for (int j = 0; j < 8; ++j) { acc0[j] = 0ull; acc1[j] = 0ull; }

            #pragma unroll
            for (int d = 0; d < DIMS; ++d) {
                const ull xp0 = pack2(x0[d]);
                const ull xp1 = pack2(x1[d]);
                const ulonglong2* ptr =
                    reinterpret_cast<const ulonglong2*>(Es + d * NUM_CODES + k0);
                ulonglong2 q0 = ptr[0];
                ulonglong2 q1 = ptr[1];
                ulonglong2 q2 = ptr[2];
                ulonglong2 q3 = ptr[3];
                acc0[0] = ffma2(xp0, q0.x, acc0[0]);  acc1[0] = ffma2(xp1, q0.x, acc1[0]);
                acc0[1] = ffma2(xp0, q0.y, acc0[1]);  acc1[1] = ffma2(xp1, q0.y, acc1[1]);
                acc0[2] = ffma2(xp0, q1.x, acc0[2]);  acc1[2] = ffma2(xp1, q1.x, acc1[2]);
                acc0[3] = ffma2(xp0, q1.y, acc0[3]);  acc1[3] = ffma2(xp1, q1.y, acc1[3]);
                acc0[4] = ffma2(xp0, q2.x, acc0[4]);  acc1[4] = ffma2(xp1, q2.x, acc1[4]);
                acc0[5] = ffma2(xp0, q2.y, acc0[5]);  acc1[5] = ffma2(xp1, q2.y, acc1[5]);
                acc0[6] = ffma2(xp0, q3.x, acc0[6]);  acc1[6] = ffma2(xp1, q3.x, acc1[6]);
                acc0[7] = ffma2(xp0, q3.y, acc0[7]);  acc1[7] = ffma2(xp1, q3.y, acc1[7]);
            }

            // dist = fl( fl(A + e2k) + fl(-2*s) ); then 16->1 FMNMX tree per pixel.
            const ull* e2q = reinterpret_cast<const ull*>(e2s + k0);
            float dl0[16], dl1[16];
            #pragma unroll
            for (int j = 0; j < 8; ++j) {
                const ull e2j = e2q[j];
                const ull d0 = fadd2(fadd2(A0p, e2j), fmul2(neg2, acc0[j]));
                const ull d1 = fadd2(fadd2(A1p, e2j), fmul2(neg2, acc1[j]));
                unpack2(d0, dl0[2 * j], dl0[2 * j + 1]);
                unpack2(d1, dl1[2 * j], dl1[2 * j + 1]);
            }
            #pragma unroll
            for (int stride = 8; stride >= 1; stride >>= 1) {
                #pragma unroll
                for (int j = 0; j < stride; ++j) {
                    dl0[j] = fminf(dl0[j], dl0[j + stride]);
                    dl1[j] = fminf(dl1[j], dl1[j + stride]);
                }
            }
            const int c = k0 >> 4;
            cmin[(c * 2 + 0) * TPB + tid] = dl0[0];
            cmin[(c * 2 + 1) * TPB + tid] = dl1[0];
        }

        // ---- Phase 2: pick winning chunk (ascending, strict < => first occurrence),
        //      recompute it bit-exactly, find first matching index. ----
        float b0 = cmin[tid], b1 = cmin[TPB + tid];
        int bc0 = 0, bc1 = 0;
        #pragma unroll
        for (int c = 1; c < NCHUNK; ++c) {
            const float v0 = cmin[(c * 2 + 0) * TPB + tid];
            const float v1 = cmin[(c * 2 + 1) * TPB + tid];
            if (v0 < b0) { b0 = v0; bc0 = c; }
            if (v1 < b1) { b1 = v1; bc1 = c; }
        }

        float dist[16];
        int bestk0 = 0, bestk1 = 0;

        chunk_dists(x0, A0p, neg2, Es, e2s, bc0 * 16, dist);
        {
            int bj = -1;
            #pragma unroll
            for (int j = 15; j >= 0; --j) if (dist[j] == b0) bj = j;   // keeps smallest j
            bestk0 = bc0 * 16 + bj;
        }
        chunk_dists(x1, A1p, neg2, Es, e2s, bc1 * 16, dist);
        {
            int bj = -1;
            #pragma unroll
            for (int j = 15; j >= 0; --j) if (dist[j] == b1) bj = j;
            bestk1 = bc1 * 16 + bj;
        }

        // ---- Write back with exact STE rounding: out = fl(x + fl(q - x)) ----
        float* po0 = out + base0;
        float* po1 = out + base0 + PAIR_OFF;
        #pragma unroll
        for (int d = 0; d < DIMS; ++d) {
            const float q0v = Es[d * NUM_CODES + bestk0];
            const float q1v = Es[d * NUM_CODES + bestk1];
            po0[d << 12] = __fadd_rn(x0[d], __fsub_rn(q0v, x0[d]));
            po1[d << 12] = __fadd_rn(x1[d], __fsub_rn(q1v, x1[d]));
        }
    }
}

extern "C" void kernel_launch(void* const* d_in, const int* in_sizes, int n_in,
                              void* d_out, int out_size) {
    const float* in  = (const float*)d_in[0];   // inputs  [32,64,64,64] fp32
    const float* emb = (const float*)d_in[1];   // embedding [512,64] fp32
    float* out = (float*)d_out;

    cudaFuncSetAttribute(vq_kernel, cudaFuncAttributeMaxDynamicSharedMemorySize, SMEM_BYTES);
    vq_kernel<<<GRID, TPB, SMEM_BYTES>>>(in, emb, out);
}